// round 10
// baseline (speedup 1.0000x reference)
#include <cuda_runtime.h>
#include <cstdint>

// out = mean( (box9(pred) - box9(target))^2 ), zero-padded on H,W.
// box9(pred)-box9(target) = box9(pred-target); separable 9x9 box.
//
// Pure register-streaming kernel: NO smem staging, NO barriers, NO shuffles
// in the main loop. Each thread owns 4 output cols of a 32-row strip.
// Per row: 3 float4 LDG per tensor (x0-4, x0, x0+4; sides are L1 hits since
// they are neighbors' center lines; centers prefetched one row ahead),
// horizontal 9-sum in registers, vertical 9-sum via an 8-deep register ring.

#define Wd    512
#define Hd    512
#define TH    32
#define NSTRIP 16
#define NIMG  64
#define NBLK  (NSTRIP * NIMG)        // 1024
#define NROWS 40                      // TH + 8 halo rows
#define NTOT  16777216.0

__device__ double       g_sum  = 0.0;
__device__ unsigned int g_done = 0;

static __device__ __forceinline__ float4 f4z() {
    return make_float4(0.f, 0.f, 0.f, 0.f);
}

__global__ __launch_bounds__(128)
void pooled_mse_kernel(const float* __restrict__ pred,
                       const float* __restrict__ target,
                       float* __restrict__ out) {
    __shared__ float s_red[4];

    const int tid  = threadIdx.x;
    const int lane = tid & 31;
    const int warp = tid >> 5;
    const int y0   = blockIdx.x * TH;
    const int img  = blockIdx.y;
    const int x0   = tid << 2;                    // own 4 cols

    const bool aleft  = (x0 != 0);
    const bool aright = (x0 != Wd - 4);

    const float* pimg = pred   + (size_t)img * (Hd * Wd);
    const float* timg = target + (size_t)img * (Hd * Wd);

    float4 ring[8];
    float4 vs  = f4z();
    float  acc = 0.0f;

    // prologue: prefetch center of row 0 (abs y0-4)
    float4 pBn = f4z(), tBn = f4z();
    {
        const int rabs = y0 - 4;
        if (rabs >= 0) {
            pBn = *(const float4*)(pimg + (size_t)rabs * Wd + x0);
            tBn = *(const float4*)(timg + (size_t)rabs * Wd + x0);
        }
    }

    #pragma unroll
    for (int r = 0; r < NROWS; r++) {
        const int  rabs  = y0 - 4 + r;
        const bool valid = ((unsigned)rabs < (unsigned)Hd);   // warp-uniform

        const float4 pB = pBn, tB = tBn;

        // prefetch next row's centers (covers DRAM latency with compute below)
        if (r < NROWS - 1) {
            const int rn = rabs + 1;
            if ((unsigned)rn < (unsigned)Hd) {
                pBn = *(const float4*)(pimg + (size_t)rn * Wd + x0);
                tBn = *(const float4*)(timg + (size_t)rn * Wd + x0);
            } else {
                pBn = f4z(); tBn = f4z();
            }
        }

        float4 hv = f4z();
        if (valid) {
            const float* prow = pimg + (size_t)rabs * Wd;
            const float* trow = timg + (size_t)rabs * Wd;
            // side loads: L1 hits (lines are neighbors' prefetched centers)
            const float4 pA = aleft  ? *(const float4*)(prow + x0 - 4) : f4z();
            const float4 tA = aleft  ? *(const float4*)(trow + x0 - 4) : f4z();
            const float4 pC = aright ? *(const float4*)(prow + x0 + 4) : f4z();
            const float4 tC = aright ? *(const float4*)(trow + x0 + 4) : f4z();

            const float4 dA = make_float4(pA.x-tA.x, pA.y-tA.y, pA.z-tA.z, pA.w-tA.w);
            const float4 dB = make_float4(pB.x-tB.x, pB.y-tB.y, pB.z-tB.z, pB.w-tB.w);
            const float4 dC = make_float4(pC.x-tC.x, pC.y-tC.y, pC.z-tC.z, pC.w-tC.w);

            const float h0 = ((dA.x + dA.y) + (dA.z + dA.w))
                           + ((dB.x + dB.y) + (dB.z + dB.w)) + dC.x;
            const float h1 = h0 - dA.x + dC.y;
            const float h2 = h1 - dA.y + dC.z;
            const float h3 = h2 - dA.z + dC.w;
            hv = make_float4(h0, h1, h2, h3);
        }

        // vertical sliding 9-sum via 8-deep ring (read-before-write)
        const float4 ho = ring[r & 7];
        ring[r & 7] = hv;
        vs.x += hv.x; vs.y += hv.y; vs.z += hv.z; vs.w += hv.w;
        if (r >= 8) {                                 // static (full unroll)
            acc += vs.x*vs.x + vs.y*vs.y + vs.z*vs.z + vs.w*vs.w;
            vs.x -= ho.x; vs.y -= ho.y; vs.z -= ho.z; vs.w -= ho.w;
        }
    }

    // ---- block reduction (4 warps) ----
    #pragma unroll
    for (int off = 16; off > 0; off >>= 1)
        acc += __shfl_xor_sync(0xFFFFFFFFu, acc, off);
    if (lane == 0) s_red[warp] = acc;
    __syncthreads();
    if (warp == 0) {
        float v = (lane < 4) ? s_red[lane] : 0.0f;
        v += __shfl_xor_sync(0xFFFFFFFFu, v, 2);
        v += __shfl_xor_sync(0xFFFFFFFFu, v, 1);
        if (lane == 0) {
            atomicAdd(&g_sum, (double)v);
            __threadfence();
            const unsigned old = atomicAdd(&g_done, 1u);
            if (old == NBLK - 1) {
                const double s = *((volatile double*)&g_sum);
                out[0] = (float)(s / (81.0 * 81.0) / NTOT);
                g_sum  = 0.0;                         // reset for graph replay
                g_done = 0u;
            }
        }
    }
}

extern "C" void kernel_launch(void* const* d_in, const int* in_sizes, int n_in,
                              void* d_out, int out_size) {
    const float* pred   = (const float*)d_in[0];
    const float* target = (const float*)d_in[1];
    float* out = (float*)d_out;
    dim3 grid(NSTRIP, NIMG);                          // 1024 blocks
    pooled_mse_kernel<<<grid, 128>>>(pred, target, out);
}

// round 11
// speedup vs baseline: 1.5973x; 1.5973x over previous
#include <cuda_runtime.h>
#include <cstdint>

// out = mean( (box9(pred) - box9(target))^2 ), zero-padded on H,W.
// box9(pred)-box9(target) = box9(pred-target); separable 9x9 box.
//
// Warp-specialized: warp 4 = TMA producer (cp.async.bulk, 8KB 4-row copies
// into a 3-slot unpadded ring per tensor), warps 0-3 = consumers (4 cols per
// thread, hsum via warp shuffles, vertical 9-sum via 8-deep register ring).
// TH=64 -> 512 blocks -> single wave at 4 blocks/SM. Consumer loop chunked
// by 6 groups so slot / ring / parity are all compile-time.

#define Wd      512
#define Hd      512
#define TH      64
#define NSTRIP  8
#define NIMG    64
#define NBLK    (NSTRIP * NIMG)      // 512
#define GR      4                     // rows per slot
#define SLOTS   3
#define NGRP    18                    // 72 rows / GR
#define ROWB    2048                  // bytes per row (512 f32)
#define NTOT    16777216.0

#define BUF_FLOATS (SLOTS * GR * Wd)          // per tensor: 6144
#define BAR_OFF    (2 * BUF_FLOATS * 4)       // 49152 bytes
#define SMEM_BYTES (BAR_OFF + 64)             // + full[3], empty[3]

__device__ double       g_sum  = 0.0;
__device__ unsigned int g_done = 0;

static __device__ __forceinline__ uint32_t s2u(const void* p) {
    uint32_t a;
    asm("{ .reg .u64 t; cvta.to.shared.u64 t, %1; cvt.u32.u64 %0, t; }"
        : "=r"(a) : "l"(p));
    return a;
}
static __device__ __forceinline__ void mbar_init(uint32_t mb, uint32_t cnt) {
    asm volatile("mbarrier.init.shared.b64 [%0], %1;" :: "r"(mb), "r"(cnt) : "memory");
}
static __device__ __forceinline__ void mbar_expect_tx(uint32_t mb, uint32_t bytes) {
    asm volatile("mbarrier.arrive.expect_tx.shared.b64 _, [%0], %1;"
                 :: "r"(mb), "r"(bytes) : "memory");
}
static __device__ __forceinline__ void mbar_arrive(uint32_t mb) {
    asm volatile("mbarrier.arrive.release.cta.shared.b64 _, [%0];"
                 :: "r"(mb) : "memory");
}
static __device__ __forceinline__ void bulk_g2s(uint32_t dst, const void* src,
                                                uint32_t bytes, uint32_t mb) {
    asm volatile(
        "cp.async.bulk.shared::cta.global.mbarrier::complete_tx::bytes [%0], [%1], %2, [%3];"
        :: "r"(dst), "l"(src), "r"(bytes), "r"(mb) : "memory");
}
static __device__ __forceinline__ void mbar_wait(uint32_t mb, uint32_t parity) {
    asm volatile(
        "{\n\t"
        ".reg .pred P1;\n\t"
        "WL_%=:\n\t"
        "mbarrier.try_wait.parity.acquire.cta.shared::cta.b64 P1, [%0], %1, 0x989680;\n\t"
        "@P1 bra.uni WD_%=;\n\t"
        "bra.uni WL_%=;\n\t"
        "WD_%=:\n\t"
        "}"
        :: "r"(mb), "r"(parity) : "memory");
}

__global__ __launch_bounds__(160)
void pooled_mse_kernel(const float* __restrict__ pred,
                       const float* __restrict__ target,
                       float* __restrict__ out) {
    extern __shared__ float sm[];
    float* pbuf = sm;                        // [SLOTS][GR][512]
    float* tbuf = sm + BUF_FLOATS;
    __shared__ float s_red[8];

    const uint32_t sbase = s2u(sm);
    const uint32_t bar   = sbase + BAR_OFF;  // full[s]=bar+8s, empty[s]=bar+24+8s

    const int tid  = threadIdx.x;
    const int lane = tid & 31;
    const int y0   = blockIdx.x * TH;
    const int img  = blockIdx.y;

    const float* pimg = pred   + (size_t)img * (Hd * Wd);
    const float* timg = target + (size_t)img * (Hd * Wd);

    if (tid == 0) {
        #pragma unroll
        for (int s = 0; s < SLOTS; s++) {
            mbar_init(bar + s * 8, 1);        // full: tx-based
            mbar_init(bar + 24 + s * 8, 4);   // empty: 4 consumer warps
        }
    }
    __syncthreads();

    float acc = 0.0f;

    if (tid < 128) {
        // ================= consumers =================
        const int x0 = tid << 2;              // own 4 cols
        float4 Hring[8];
        float4 vs = make_float4(0.f, 0.f, 0.f, 0.f);

        #pragma unroll 1
        for (int g0 = 0; g0 < NGRP; g0 += 6) {      // 3 chunks of 6 groups
            #pragma unroll
            for (int gi = 0; gi < 6; gi++) {
                const int g    = g0 + gi;
                const int slot = gi % 3;             // compile-time
                const uint32_t par = (gi >= 3) ? 1u : 0u;  // compile-time
                mbar_wait(bar + slot * 8, par);

                #pragma unroll
                for (int i = 0; i < GR; i++) {
                    const int rr   = gi * GR + i;    // compile-time row-in-chunk
                    const int rabs = y0 - 4 + g * GR + i;
                    const bool valid = ((unsigned)rabs < (unsigned)Hd);

                    const float* prow = pbuf + (slot * GR + i) * Wd;
                    const float* trow = tbuf + (slot * GR + i) * Wd;

                    float4 d = make_float4(0.f, 0.f, 0.f, 0.f);
                    if (valid) {
                        const float4 p = *(const float4*)(prow + x0);
                        const float4 t = *(const float4*)(trow + x0);
                        d = make_float4(p.x - t.x, p.y - t.y, p.z - t.z, p.w - t.w);
                    }

                    float4 dl, dr;
                    dl.x = __shfl_up_sync(0xFFFFFFFFu, d.x, 1);
                    dl.y = __shfl_up_sync(0xFFFFFFFFu, d.y, 1);
                    dl.z = __shfl_up_sync(0xFFFFFFFFu, d.z, 1);
                    dl.w = __shfl_up_sync(0xFFFFFFFFu, d.w, 1);
                    dr.x = __shfl_down_sync(0xFFFFFFFFu, d.x, 1);
                    dr.y = __shfl_down_sync(0xFFFFFFFFu, d.y, 1);
                    dr.z = __shfl_down_sync(0xFFFFFFFFu, d.z, 1);
                    dr.w = __shfl_down_sync(0xFFFFFFFFu, d.w, 1);
                    if (lane == 0) {              // cross-warp / image-left halo
                        dl = make_float4(0.f, 0.f, 0.f, 0.f);
                        if (valid && x0 != 0) {
                            const float4 p = *(const float4*)(prow + x0 - 4);
                            const float4 t = *(const float4*)(trow + x0 - 4);
                            dl = make_float4(p.x-t.x, p.y-t.y, p.z-t.z, p.w-t.w);
                        }
                    }
                    if (lane == 31) {             // cross-warp / image-right halo
                        dr = make_float4(0.f, 0.f, 0.f, 0.f);
                        if (valid && x0 != Wd - 4) {
                            const float4 p = *(const float4*)(prow + x0 + 4);
                            const float4 t = *(const float4*)(trow + x0 + 4);
                            dr = make_float4(p.x-t.x, p.y-t.y, p.z-t.z, p.w-t.w);
                        }
                    }

                    const float h0 = ((dl.x + dl.y) + (dl.z + dl.w))
                                   + ((d.x + d.y) + (d.z + d.w)) + dr.x;
                    const float h1 = h0 - dl.x + dr.y;
                    const float h2 = h1 - dl.y + dr.z;
                    const float h3 = h2 - dl.z + dr.w;
                    const float4 hv = make_float4(h0, h1, h2, h3);

                    // 8-deep ring, read-before-write; rr&7 compile-time since
                    // chunks are 24 rows (multiple of 8)
                    const float4 ho = Hring[rr & 7];
                    Hring[rr & 7] = hv;
                    vs.x += hv.x; vs.y += hv.y; vs.z += hv.z; vs.w += hv.w;
                    if (g * GR + i >= 8) {        // compile-time per chunk/row
                        acc += vs.x*vs.x + vs.y*vs.y + vs.z*vs.z + vs.w*vs.w;
                        vs.x -= ho.x; vs.y -= ho.y; vs.z -= ho.z; vs.w -= ho.w;
                    }
                }
                if (lane == 0) mbar_arrive(bar + 24 + slot * 8);
            }
        }
    } else if (tid == 128) {
        // ================= producer =================
        asm volatile("fence.proxy.async.shared::cta;" ::: "memory");
        const uint32_t pbuf_u = sbase;
        const uint32_t tbuf_u = sbase + BUF_FLOATS * 4;
        #pragma unroll 1
        for (int g0 = 0; g0 < NGRP; g0 += 6) {
            #pragma unroll
            for (int gi = 0; gi < 6; gi++) {
                const int g    = g0 + gi;
                const int slot = gi % 3;
                const uint32_t par = (gi >= 3) ? 1u : 0u;
                // fresh-barrier trick: first 3 waits (parity 1) pass instantly
                mbar_wait(bar + 24 + slot * 8, 1u ^ par);

                const int rbase = y0 - 4 + GR * g;
                int i0 = rbase < 0 ? -rbase : 0;
                int i1 = (rbase + GR > Hd) ? (Hd - rbase) : GR;
                if (i1 < i0) i1 = i0;
                const int n = i1 - i0;
                const uint32_t mb = bar + slot * 8;
                mbar_expect_tx(mb, (uint32_t)(n * ROWB * 2));
                if (n > 0) {
                    const uint32_t off = (uint32_t)(slot * GR + i0) * ROWB;
                    const size_t gofs = (size_t)(rbase + i0) * Wd;
                    bulk_g2s(pbuf_u + off, pimg + gofs, (uint32_t)(n * ROWB), mb);
                    bulk_g2s(tbuf_u + off, timg + gofs, (uint32_t)(n * ROWB), mb);
                }
            }
        }
    }

    // ---- block reduction (5 warps) ----
    const int warp = tid >> 5;
    #pragma unroll
    for (int off = 16; off > 0; off >>= 1)
        acc += __shfl_xor_sync(0xFFFFFFFFu, acc, off);
    if (tid == 0) { s_red[5] = 0.f; s_red[6] = 0.f; s_red[7] = 0.f; }
    __syncthreads();
    if (lane == 0) s_red[warp] = acc;
    __syncthreads();
    if (warp == 0) {
        float v = (lane < 8) ? s_red[lane] : 0.0f;
        #pragma unroll
        for (int off = 4; off > 0; off >>= 1)
            v += __shfl_xor_sync(0xFFFFFFFFu, v, off);
        if (lane == 0) {
            atomicAdd(&g_sum, (double)v);
            __threadfence();
            const unsigned old = atomicAdd(&g_done, 1u);
            if (old == NBLK - 1) {
                const double s = *((volatile double*)&g_sum);
                out[0] = (float)(s / (81.0 * 81.0) / NTOT);
                g_sum  = 0.0;                 // reset for next graph replay
                g_done = 0u;
            }
        }
    }
}

extern "C" void kernel_launch(void* const* d_in, const int* in_sizes, int n_in,
                              void* d_out, int out_size) {
    const float* pred   = (const float*)d_in[0];
    const float* target = (const float*)d_in[1];
    float* out = (float*)d_out;
    cudaFuncSetAttribute(pooled_mse_kernel,
                         cudaFuncAttributeMaxDynamicSharedMemorySize, SMEM_BYTES);
    dim3 grid(NSTRIP, NIMG);                  // 512 blocks: single wave
    pooled_mse_kernel<<<grid, 160, SMEM_BYTES>>>(pred, target, out);
}